// round 2
// baseline (speedup 1.0000x reference)
#include <cuda_runtime.h>
#include <cstdint>
#include <cstddef>

#define L_SEQ  2048
#define NHID_C 512
#define DMODEL 1024
#define BATCH  8

// Scratch (allocation-free): qkv = [b][3072][2048], att2 = [b][1024][2048]
__device__ float g_qkv [(size_t)BATCH * 3 * DMODEL * L_SEQ];
__device__ float g_att2[(size_t)BATCH * DMODEL * L_SEQ];

__device__ __forceinline__ unsigned f2tf32(float x) {
    unsigned r;
    asm("cvt.rna.tf32.f32 %0, %1;" : "=r"(r) : "f"(x));
    return r;
}

// ---------------------------------------------------------------------------
// Generic batched GEMM:  O[b, m, n] = sum_k W[k, m] * X[b, k, n] + bias[m]
//   W stored (Kdim x Mper) row-major (m contiguous)  -- matches wq/wk/wv/wo
//   X stored (Kdim x 2048) row-major per batch       -- matches x / att2
//   O stored (Mtot x 2048) row-major per batch
// CTA tile 128x128x32, 8 warps (4x2), warp tile 32x64, mma m16n8k8 tf32.
// The CTA picks W0/W1/W2 by m0/Mper so one launch covers concat(wq,wk,wv).
// ---------------------------------------------------------------------------
__global__ void __launch_bounds__(256, 1) gemm_tf32_kernel(
    const float* __restrict__ X, size_t xStrideB,
    const float* __restrict__ W0, const float* __restrict__ W1, const float* __restrict__ W2,
    const float* __restrict__ bias0, const float* __restrict__ bias1, const float* __restrict__ bias2,
    float* __restrict__ O, size_t oStrideB,
    int Kdim, int Mper)
{
    const int LDA = 132, LDB = 132;
    __shared__ float As[32 * 132];  // As[k][m], tf32-rounded
    __shared__ float Bs[32 * 132];  // Bs[k][n], tf32-rounded

    const int b  = blockIdx.z;
    const int m0 = blockIdx.y * 128;
    const int n0 = blockIdx.x * 128;
    const int widx = m0 / Mper;
    const float* W    = (widx == 0) ? W0 : ((widx == 1) ? W1 : W2);
    const float* bias = (widx == 0) ? bias0 : ((widx == 1) ? bias1 : bias2);
    const int mloc = m0 - widx * Mper;
    const float* Xb = X + (size_t)b * xStrideB;
    float*       Ob = O + (size_t)b * oStrideB;

    const int tid  = threadIdx.x;
    const int warp = tid >> 5, lane = tid & 31;
    const int wm = (warp >> 1) * 32;   // warp M offset (4 warps along M)
    const int wn = (warp & 1) * 64;    // warp N offset (2 warps along N)
    const int g  = lane >> 2;          // groupID (0..7)
    const int tq = lane & 3;           // threadID_in_group (0..3)

    float acc[2][8][4];
    #pragma unroll
    for (int i = 0; i < 2; i++)
        #pragma unroll
        for (int j = 0; j < 8; j++)
            #pragma unroll
            for (int r = 0; r < 4; r++) acc[i][j][r] = 0.f;

    for (int kt = 0; kt < Kdim; kt += 32) {
        // Load A tile: 32 x 128 from W[k, m], convert to tf32.
        #pragma unroll
        for (int p = 0; p < 4; p++) {
            int e  = p * 256 + tid;        // float4 unit index 0..1023
            int kr = e >> 5;
            int mq = (e & 31) << 2;
            float4 v = *reinterpret_cast<const float4*>(
                &W[(size_t)(kt + kr) * Mper + mloc + mq]);
            float4 s;
            s.x = __uint_as_float(f2tf32(v.x));
            s.y = __uint_as_float(f2tf32(v.y));
            s.z = __uint_as_float(f2tf32(v.z));
            s.w = __uint_as_float(f2tf32(v.w));
            *reinterpret_cast<float4*>(&As[kr * LDA + mq]) = s;
        }
        // Load B tile: 32 x 128 from X[k, n], convert to tf32.
        #pragma unroll
        for (int p = 0; p < 4; p++) {
            int e  = p * 256 + tid;
            int kr = e >> 5;
            int nq = (e & 31) << 2;
            float4 v = *reinterpret_cast<const float4*>(
                &Xb[(size_t)(kt + kr) * L_SEQ + n0 + nq]);
            float4 s;
            s.x = __uint_as_float(f2tf32(v.x));
            s.y = __uint_as_float(f2tf32(v.y));
            s.z = __uint_as_float(f2tf32(v.z));
            s.w = __uint_as_float(f2tf32(v.w));
            *reinterpret_cast<float4*>(&Bs[kr * LDB + nq]) = s;
        }
        __syncthreads();

        #pragma unroll
        for (int kk = 0; kk < 32; kk += 8) {
            unsigned a[2][4];
            #pragma unroll
            for (int i = 0; i < 2; i++) {
                int mr = wm + i * 16;
                a[i][0] = __float_as_uint(As[(kk + tq)     * LDA + mr + g]);
                a[i][1] = __float_as_uint(As[(kk + tq)     * LDA + mr + g + 8]);
                a[i][2] = __float_as_uint(As[(kk + tq + 4) * LDA + mr + g]);
                a[i][3] = __float_as_uint(As[(kk + tq + 4) * LDA + mr + g + 8]);
            }
            unsigned bb[8][2];
            #pragma unroll
            for (int j = 0; j < 8; j++) {
                bb[j][0] = __float_as_uint(Bs[(kk + tq)     * LDB + wn + j * 8 + g]);
                bb[j][1] = __float_as_uint(Bs[(kk + tq + 4) * LDB + wn + j * 8 + g]);
            }
            #pragma unroll
            for (int i = 0; i < 2; i++)
                #pragma unroll
                for (int j = 0; j < 8; j++) {
                    asm("mma.sync.aligned.m16n8k8.row.col.f32.tf32.tf32.f32 "
                        "{%0,%1,%2,%3}, {%4,%5,%6,%7}, {%8,%9}, {%0,%1,%2,%3};\n"
                        : "+f"(acc[i][j][0]), "+f"(acc[i][j][1]),
                          "+f"(acc[i][j][2]), "+f"(acc[i][j][3])
                        : "r"(a[i][0]), "r"(a[i][1]), "r"(a[i][2]), "r"(a[i][3]),
                          "r"(bb[j][0]), "r"(bb[j][1]));
                }
        }
        __syncthreads();
    }

    // Epilogue: add bias, store float2 pairs (coalesced-ish, aligned).
    #pragma unroll
    for (int i = 0; i < 2; i++) {
        int r0 = wm + i * 16 + g;
        float bv0 = bias[mloc + r0];
        float bv1 = bias[mloc + r0 + 8];
        #pragma unroll
        for (int j = 0; j < 8; j++) {
            int col = n0 + wn + j * 8 + tq * 2;
            float2 v01 = make_float2(acc[i][j][0] + bv0, acc[i][j][1] + bv0);
            float2 v23 = make_float2(acc[i][j][2] + bv1, acc[i][j][3] + bv1);
            *reinterpret_cast<float2*>(&Ob[(size_t)(m0 + r0)     * L_SEQ + col]) = v01;
            *reinterpret_cast<float2*>(&Ob[(size_t)(m0 + r0 + 8) * L_SEQ + col]) = v23;
        }
    }
}

// ---------------------------------------------------------------------------
// Attention: per (b, h, 128 consecutive l). For channel c'=h*64+d, tap w:
//   f = 3c'+w; src channel = f&1023; l-offset = (f>>10)-1 (zero-padded).
// logits = sum_d q*k / 8, softmax over 3 taps, att = sum_w alpha*v.
// Output written in the scrambled att2 layout:
//   att2[b, h*64 + (l>>5), (l&31)*64 + d]
// -> this block covers 4 full contiguous rows; staged via XOR-swizzled smem
//    so both STS and the final STG are conflict-free / coalesced.
// ---------------------------------------------------------------------------
__global__ void __launch_bounds__(128) attn_kernel(float* __restrict__ att2)
{
    __shared__ float att_s[4][2048];
    const int b = blockIdx.z, h = blockIdx.y;
    const int l0 = blockIdx.x * 128;
    const int t = threadIdx.x;
    const int l = l0 + t;
    const float* base = g_qkv + (size_t)b * 3 * DMODEL * L_SEQ;
    const float* Q = base;
    const float* K = base + (size_t)DMODEL * L_SEQ;
    const float* V = base + (size_t)2 * DMODEL * L_SEQ;
    const int c0 = h * 64;

    float lg0 = 0.f, lg1 = 0.f, lg2 = 0.f;
    #pragma unroll 8
    for (int d = 0; d < 64; d++) {
        int cp = c0 + d;
        float qv = Q[(size_t)cp * L_SEQ + l];
        int f = 3 * cp;
        #pragma unroll
        for (int w = 0; w < 3; w++) {
            int ff = f + w;
            int cc = ff & 1023;
            int ll = l + (ff >> 10) - 1;
            float kv = (ll >= 0 && ll < L_SEQ) ? K[(size_t)cc * L_SEQ + ll] : 0.f;
            if (w == 0) lg0 += qv * kv;
            else if (w == 1) lg1 += qv * kv;
            else lg2 += qv * kv;
        }
    }
    float m  = fmaxf(lg0, fmaxf(lg1, lg2));
    float e0 = expf((lg0 - m) * 0.125f);
    float e1 = expf((lg1 - m) * 0.125f);
    float e2 = expf((lg2 - m) * 0.125f);
    float inv = 1.f / (e0 + e1 + e2);
    float a0 = e0 * inv, a1 = e1 * inv, a2 = e2 * inv;

    const int r = t >> 5, ln = t & 31;
    #pragma unroll 8
    for (int d = 0; d < 64; d++) {
        int cp = c0 + d;
        int f = 3 * cp;
        float s = 0.f;
        #pragma unroll
        for (int w = 0; w < 3; w++) {
            int ff = f + w;
            int cc = ff & 1023;
            int ll = l + (ff >> 10) - 1;
            float vv = (ll >= 0 && ll < L_SEQ) ? V[(size_t)cc * L_SEQ + ll] : 0.f;
            s += (w == 0 ? a0 : (w == 1 ? a1 : a2)) * vv;
        }
        att_s[r][ln * 64 + (d ^ ln)] = s;   // XOR swizzle: conflict-free STS
    }
    __syncthreads();

    float* out = att2 + (size_t)b * DMODEL * L_SEQ
                      + (size_t)(h * 64 + (l0 >> 5)) * L_SEQ;
    for (int j = t; j < 4 * 2048; j += 128) {
        int rr  = j >> 11;
        int col = j & 2047;
        int llx = col >> 6;
        int dd  = col & 63;
        out[(size_t)rr * L_SEQ + col] = att_s[rr][(llx << 6) + (dd ^ llx)];
    }
}

// ---------------------------------------------------------------------------
extern "C" void kernel_launch(void* const* d_in, const int* in_sizes, int n_in,
                              void* d_out, int out_size)
{
    const float* x  = (const float*)d_in[0];
    const float* wq = (const float*)d_in[1];
    const float* bq = (const float*)d_in[2];
    const float* wk = (const float*)d_in[3];
    const float* bk = (const float*)d_in[4];
    const float* wv = (const float*)d_in[5];
    const float* bv = (const float*)d_in[6];
    const float* wo = (const float*)d_in[7];
    const float* bo = (const float*)d_in[8];
    float* out = (float*)d_out;

    float* qkv;  cudaGetSymbolAddress((void**)&qkv,  g_qkv);
    float* att2; cudaGetSymbolAddress((void**)&att2, g_att2);

    // GEMM1: QKV projections. M = 3072 (q|k|v), K = 512, N = 2048, per batch.
    gemm_tf32_kernel<<<dim3(16, 24, BATCH), 256>>>(
        x, (size_t)NHID_C * L_SEQ,
        wq, wk, wv, bq, bk, bv,
        qkv, (size_t)3 * DMODEL * L_SEQ,
        NHID_C, DMODEL);

    // Attention: 16 l-tiles x 16 heads x 8 batches.
    attn_kernel<<<dim3(16, 16, BATCH), 128>>>(att2);

    // GEMM3: output projection. M = 512, K = 1024, N = 2048, per batch.
    gemm_tf32_kernel<<<dim3(16, 4, BATCH), 256>>>(
        att2, (size_t)DMODEL * L_SEQ,
        wo, wo, wo, bo, bo, bo,
        out, (size_t)NHID_C * L_SEQ,
        DMODEL, NHID_C);
}

// round 3
// speedup vs baseline: 1.3206x; 1.3206x over previous
#include <cuda_runtime.h>
#include <cstdint>
#include <cstddef>

#define L_SEQ  2048
#define NHID_C 512
#define DMODEL 1024
#define BATCH  8

// Scratch (allocation-free): qkv = [b][3072][2048], att2 = [b][1024][2048]
__device__ float g_qkv [(size_t)BATCH * 3 * DMODEL * L_SEQ];
__device__ float g_att2[(size_t)BATCH * DMODEL * L_SEQ];

__device__ __forceinline__ unsigned f2tf32(float x) {
    unsigned r;
    asm("cvt.rna.tf32.f32 %0, %1;" : "=r"(r) : "f"(x));
    return r;
}

// ---------------------------------------------------------------------------
// Batched GEMM:  O[b, m, n] = sum_k W[k, m] * X[b, k, n] + bias[m]
// CTA tile 128x128x32, 8 warps (4x2), warp tile 32x64, mma m16n8k8 tf32.
// 4-stage cp.async pipeline, LDA/LDB = 136 (conflict-free fragment LDS).
// ---------------------------------------------------------------------------
#define LDS_   136
#define TS_    (32 * LDS_)          // floats per tile buffer (4352)
#define STAGES 4

__global__ void __launch_bounds__(256, 1) gemm_tf32_kernel(
    const float* __restrict__ X, size_t xStrideB,
    const float* __restrict__ W0, const float* __restrict__ W1, const float* __restrict__ W2,
    const float* __restrict__ bias0, const float* __restrict__ bias1, const float* __restrict__ bias2,
    float* __restrict__ O, size_t oStrideB,
    int Kdim, int Mper)
{
    extern __shared__ float smem[];
    float* As = smem;                   // [STAGES][TS_]
    float* Bs = smem + STAGES * TS_;    // [STAGES][TS_]

    const int b  = blockIdx.z;
    const int m0 = blockIdx.y * 128;
    const int n0 = blockIdx.x * 128;
    const int widx = m0 / Mper;
    const float* W    = (widx == 0) ? W0 : ((widx == 1) ? W1 : W2);
    const float* bias = (widx == 0) ? bias0 : ((widx == 1) ? bias1 : bias2);
    const int mloc = m0 - widx * Mper;
    const float* Xb = X + (size_t)b * xStrideB;
    float*       Ob = O + (size_t)b * oStrideB;

    const int tid  = threadIdx.x;
    const int warp = tid >> 5, lane = tid & 31;
    const int wm = (warp >> 1) * 32;
    const int wn = (warp & 1) * 64;
    const int g  = lane >> 2;
    const int tq = lane & 3;

    const unsigned sBase = (unsigned)__cvta_generic_to_shared(smem);

    // per-thread copy coordinates (16B units): 4 chunks per tile per side
    const int kr_[4] = { tid >> 5, (256 + tid) >> 5, (512 + tid) >> 5, (768 + tid) >> 5 };
    const int cq_ = (tid & 31) << 2;   // column (m or n) offset, 0..124

    float acc[2][8][4];
    #pragma unroll
    for (int i = 0; i < 2; i++)
        #pragma unroll
        for (int j = 0; j < 8; j++)
            #pragma unroll
            for (int r = 0; r < 4; r++) acc[i][j][r] = 0.f;

    const int T = Kdim >> 5;   // number of 32-k tiles

    // issue cp.async for tile t into stage s (caller guards t < T)
    auto issue = [&](int t, int s) {
        const int kt = t << 5;
        #pragma unroll
        for (int p = 0; p < 4; p++) {
            const float* src = &W[(size_t)(kt + kr_[p]) * Mper + mloc + cq_];
            unsigned dst = sBase + (unsigned)((s * TS_ + kr_[p] * LDS_ + cq_) << 2);
            asm volatile("cp.async.ca.shared.global [%0], [%1], 16;\n" :: "r"(dst), "l"(src));
        }
        #pragma unroll
        for (int p = 0; p < 4; p++) {
            const float* src = &Xb[(size_t)(kt + kr_[p]) * L_SEQ + n0 + cq_];
            unsigned dst = sBase + (unsigned)(((STAGES + s) * TS_ + kr_[p] * LDS_ + cq_) << 2);
            asm volatile("cp.async.cg.shared.global [%0], [%1], 16;\n" :: "r"(dst), "l"(src));
        }
    };

    // prologue: stages 0..2
    #pragma unroll
    for (int t = 0; t < STAGES - 1; t++) {
        if (t < T) issue(t, t);
        asm volatile("cp.async.commit_group;\n");
    }

    for (int t = 0; t < T; t++) {
        asm volatile("cp.async.wait_group %0;\n" :: "n"(STAGES - 2));
        __syncthreads();

        // prefetch tile t+3
        if (t + STAGES - 1 < T) issue(t + STAGES - 1, (t + STAGES - 1) & (STAGES - 1));
        asm volatile("cp.async.commit_group;\n");

        const float* Ab = As + (t & (STAGES - 1)) * TS_;
        const float* Bb = Bs + (t & (STAGES - 1)) * TS_;

        #pragma unroll
        for (int kk = 0; kk < 32; kk += 8) {
            unsigned a[2][4];
            #pragma unroll
            for (int i = 0; i < 2; i++) {
                int mr = wm + i * 16;
                a[i][0] = f2tf32(Ab[(kk + tq)     * LDS_ + mr + g]);
                a[i][1] = f2tf32(Ab[(kk + tq)     * LDS_ + mr + g + 8]);
                a[i][2] = f2tf32(Ab[(kk + tq + 4) * LDS_ + mr + g]);
                a[i][3] = f2tf32(Ab[(kk + tq + 4) * LDS_ + mr + g + 8]);
            }
            unsigned bb[8][2];
            #pragma unroll
            for (int j = 0; j < 8; j++) {
                bb[j][0] = f2tf32(Bb[(kk + tq)     * LDS_ + wn + j * 8 + g]);
                bb[j][1] = f2tf32(Bb[(kk + tq + 4) * LDS_ + wn + j * 8 + g]);
            }
            #pragma unroll
            for (int i = 0; i < 2; i++)
                #pragma unroll
                for (int j = 0; j < 8; j++) {
                    asm("mma.sync.aligned.m16n8k8.row.col.f32.tf32.tf32.f32 "
                        "{%0,%1,%2,%3}, {%4,%5,%6,%7}, {%8,%9}, {%0,%1,%2,%3};\n"
                        : "+f"(acc[i][j][0]), "+f"(acc[i][j][1]),
                          "+f"(acc[i][j][2]), "+f"(acc[i][j][3])
                        : "r"(a[i][0]), "r"(a[i][1]), "r"(a[i][2]), "r"(a[i][3]),
                          "r"(bb[j][0]), "r"(bb[j][1]));
                }
        }
    }

    // Epilogue: add bias, store float2 pairs.
    #pragma unroll
    for (int i = 0; i < 2; i++) {
        int r0 = wm + i * 16 + g;
        float bv0 = bias[mloc + r0];
        float bv1 = bias[mloc + r0 + 8];
        #pragma unroll
        for (int j = 0; j < 8; j++) {
            int col = n0 + wn + j * 8 + tq * 2;
            float2 v01 = make_float2(acc[i][j][0] + bv0, acc[i][j][1] + bv0);
            float2 v23 = make_float2(acc[i][j][2] + bv1, acc[i][j][3] + bv1);
            *reinterpret_cast<float2*>(&Ob[(size_t)(m0 + r0)     * L_SEQ + col]) = v01;
            *reinterpret_cast<float2*>(&Ob[(size_t)(m0 + r0 + 8) * L_SEQ + col]) = v23;
        }
    }
}

// ---------------------------------------------------------------------------
// Attention (unchanged): per (b, h, 128 consecutive l).
// ---------------------------------------------------------------------------
__global__ void __launch_bounds__(128) attn_kernel(float* __restrict__ att2)
{
    __shared__ float att_s[4][2048];
    const int b = blockIdx.z, h = blockIdx.y;
    const int l0 = blockIdx.x * 128;
    const int t = threadIdx.x;
    const int l = l0 + t;
    const float* base = g_qkv + (size_t)b * 3 * DMODEL * L_SEQ;
    const float* Q = base;
    const float* K = base + (size_t)DMODEL * L_SEQ;
    const float* V = base + (size_t)2 * DMODEL * L_SEQ;
    const int c0 = h * 64;

    float lg0 = 0.f, lg1 = 0.f, lg2 = 0.f;
    #pragma unroll 8
    for (int d = 0; d < 64; d++) {
        int cp = c0 + d;
        float qv = Q[(size_t)cp * L_SEQ + l];
        int f = 3 * cp;
        #pragma unroll
        for (int w = 0; w < 3; w++) {
            int ff = f + w;
            int cc = ff & 1023;
            int ll = l + (ff >> 10) - 1;
            float kv = (ll >= 0 && ll < L_SEQ) ? K[(size_t)cc * L_SEQ + ll] : 0.f;
            if (w == 0) lg0 += qv * kv;
            else if (w == 1) lg1 += qv * kv;
            else lg2 += qv * kv;
        }
    }
    float m  = fmaxf(lg0, fmaxf(lg1, lg2));
    float e0 = expf((lg0 - m) * 0.125f);
    float e1 = expf((lg1 - m) * 0.125f);
    float e2 = expf((lg2 - m) * 0.125f);
    float inv = 1.f / (e0 + e1 + e2);
    float a0 = e0 * inv, a1 = e1 * inv, a2 = e2 * inv;

    const int r = t >> 5, ln = t & 31;
    #pragma unroll 8
    for (int d = 0; d < 64; d++) {
        int cp = c0 + d;
        int f = 3 * cp;
        float s = 0.f;
        #pragma unroll
        for (int w = 0; w < 3; w++) {
            int ff = f + w;
            int cc = ff & 1023;
            int ll = l + (ff >> 10) - 1;
            float vv = (ll >= 0 && ll < L_SEQ) ? V[(size_t)cc * L_SEQ + ll] : 0.f;
            s += (w == 0 ? a0 : (w == 1 ? a1 : a2)) * vv;
        }
        att_s[r][ln * 64 + (d ^ ln)] = s;   // XOR swizzle: conflict-free STS
    }
    __syncthreads();

    float* out = att2 + (size_t)b * DMODEL * L_SEQ
                      + (size_t)(h * 64 + (l0 >> 5)) * L_SEQ;
    for (int j = t; j < 4 * 2048; j += 128) {
        int rr  = j >> 11;
        int col = j & 2047;
        int llx = col >> 6;
        int dd  = col & 63;
        out[(size_t)rr * L_SEQ + col] = att_s[rr][(llx << 6) + (dd ^ llx)];
    }
}

// ---------------------------------------------------------------------------
extern "C" void kernel_launch(void* const* d_in, const int* in_sizes, int n_in,
                              void* d_out, int out_size)
{
    const float* x  = (const float*)d_in[0];
    const float* wq = (const float*)d_in[1];
    const float* bq = (const float*)d_in[2];
    const float* wk = (const float*)d_in[3];
    const float* bk = (const float*)d_in[4];
    const float* wv = (const float*)d_in[5];
    const float* bv = (const float*)d_in[6];
    const float* wo = (const float*)d_in[7];
    const float* bo = (const float*)d_in[8];
    float* out = (float*)d_out;

    float* qkv;  cudaGetSymbolAddress((void**)&qkv,  g_qkv);
    float* att2; cudaGetSymbolAddress((void**)&att2, g_att2);

    const int smemBytes = STAGES * 2 * TS_ * (int)sizeof(float);  // 139264
    cudaFuncSetAttribute(gemm_tf32_kernel,
                         cudaFuncAttributeMaxDynamicSharedMemorySize, smemBytes);

    // GEMM1: QKV projections. M = 3072 (q|k|v), K = 512, N = 2048, per batch.
    gemm_tf32_kernel<<<dim3(16, 24, BATCH), 256, smemBytes>>>(
        x, (size_t)NHID_C * L_SEQ,
        wq, wk, wv, bq, bk, bv,
        qkv, (size_t)3 * DMODEL * L_SEQ,
        NHID_C, DMODEL);

    // Attention: 16 l-tiles x 16 heads x 8 batches.
    attn_kernel<<<dim3(16, 16, BATCH), 128>>>(att2);

    // GEMM3: output projection. M = 512, K = 1024, N = 2048, per batch.
    gemm_tf32_kernel<<<dim3(16, 4, BATCH), 256, smemBytes>>>(
        att2, (size_t)DMODEL * L_SEQ,
        wo, wo, wo, bo, bo, bo,
        out, (size_t)NHID_C * L_SEQ,
        DMODEL, NHID_C);
}

// round 5
// speedup vs baseline: 1.6023x; 1.2133x over previous
#include <cuda_runtime.h>
#include <cstdint>
#include <cstddef>

#define L_SEQ  2048
#define NHID_C 512
#define DMODEL 1024
#define BATCH  8

// Scratch (allocation-free)
__device__ float g_qkv [(size_t)BATCH * 3 * DMODEL * L_SEQ];   // tf32-rounded
__device__ float g_att2[(size_t)BATCH * DMODEL * L_SEQ];       // tf32-rounded
__device__ float g_xr  [(size_t)BATCH * NHID_C * L_SEQ];       // tf32-rounded x
__device__ float g_wr  [4 * 512 * 1024];                       // wq|wk|wv|wo tf32

__device__ __forceinline__ unsigned f2tf32(float x) {
    unsigned r;
    asm("cvt.rna.tf32.f32 %0, %1;" : "=r"(r) : "f"(x));
    return r;
}
__device__ __forceinline__ float rnd_tf32(float x) {
    return __uint_as_float(f2tf32(x));
}

// ---------------------------------------------------------------------------
// Pre-convert kernels: fp32 -> tf32-rounded fp32 (vectorized).
// ---------------------------------------------------------------------------
__global__ void cvt_x_kernel(const float* __restrict__ src, float* __restrict__ dst, int n4)
{
    int i = blockIdx.x * blockDim.x + threadIdx.x;
    int stride = gridDim.x * blockDim.x;
    for (; i < n4; i += stride) {
        float4 v = reinterpret_cast<const float4*>(src)[i];
        v.x = rnd_tf32(v.x); v.y = rnd_tf32(v.y);
        v.z = rnd_tf32(v.z); v.w = rnd_tf32(v.w);
        reinterpret_cast<float4*>(dst)[i] = v;
    }
}

__global__ void cvt_w_kernel(const float* __restrict__ w0, const float* __restrict__ w1,
                             const float* __restrict__ w2, const float* __restrict__ w3,
                             float* __restrict__ dst)
{
    // each weight = 524288 elements = 131072 float4; total 4 segments
    int i = blockIdx.x * blockDim.x + threadIdx.x;
    int stride = gridDim.x * blockDim.x;
    for (; i < 4 * 131072; i += stride) {
        int seg = i >> 17;
        int loc = i & 131071;
        const float* s = (seg == 0) ? w0 : (seg == 1) ? w1 : (seg == 2) ? w2 : w3;
        float4 v = reinterpret_cast<const float4*>(s)[loc];
        v.x = rnd_tf32(v.x); v.y = rnd_tf32(v.y);
        v.z = rnd_tf32(v.z); v.w = rnd_tf32(v.w);
        reinterpret_cast<float4*>(dst)[i] = v;
    }
}

// ---------------------------------------------------------------------------
// Batched GEMM:  O[b, m, n] = sum_k W[k, m] * X[b, k, n] + bias[m]
// All operands already tf32-rounded. CTA tile 128x128x32, 8 warps (4x2),
// warp tile 32x64, mma m16n8k8. 3-stage cp.async pipeline, 2 CTAs/SM.
// ---------------------------------------------------------------------------
#define LDS_   136
#define TS_    (32 * LDS_)
#define STAGES 3

__global__ void __launch_bounds__(256, 2) gemm_tf32_kernel(
    const float* __restrict__ X, size_t xStrideB,
    const float* __restrict__ W0, const float* __restrict__ W1, const float* __restrict__ W2,
    const float* __restrict__ bias0, const float* __restrict__ bias1, const float* __restrict__ bias2,
    float* __restrict__ O, size_t oStrideB,
    int Kdim, int Mper, int roundOut)
{
    extern __shared__ float smem[];
    float* As = smem;
    float* Bs = smem + STAGES * TS_;

    const int b  = blockIdx.z;
    const int m0 = blockIdx.y * 128;
    const int n0 = blockIdx.x * 128;
    const int widx = m0 / Mper;
    const float* W    = (widx == 0) ? W0 : ((widx == 1) ? W1 : W2);
    const float* bias = (widx == 0) ? bias0 : ((widx == 1) ? bias1 : bias2);
    const int mloc = m0 - widx * Mper;
    const float* Xb = X + (size_t)b * xStrideB;
    float*       Ob = O + (size_t)b * oStrideB;

    const int tid  = threadIdx.x;
    const int warp = tid >> 5, lane = tid & 31;
    const int wm = (warp >> 1) * 32;
    const int wn = (warp & 1) * 64;
    const int g  = lane >> 2;
    const int tq = lane & 3;

    const unsigned sBase = (unsigned)__cvta_generic_to_shared(smem);

    const int kr_[4] = { tid >> 5, (256 + tid) >> 5, (512 + tid) >> 5, (768 + tid) >> 5 };
    const int cq_ = (tid & 31) << 2;

    float acc[2][8][4];
    #pragma unroll
    for (int i = 0; i < 2; i++)
        #pragma unroll
        for (int j = 0; j < 8; j++)
            #pragma unroll
            for (int r = 0; r < 4; r++) acc[i][j][r] = 0.f;

    const int T = Kdim >> 5;

    auto issue = [&](int t, int s) {
        const int kt = t << 5;
        #pragma unroll
        for (int p = 0; p < 4; p++) {
            const float* src = &W[(size_t)(kt + kr_[p]) * Mper + mloc + cq_];
            unsigned dst = sBase + (unsigned)((s * TS_ + kr_[p] * LDS_ + cq_) << 2);
            asm volatile("cp.async.ca.shared.global [%0], [%1], 16;\n" :: "r"(dst), "l"(src));
        }
        #pragma unroll
        for (int p = 0; p < 4; p++) {
            const float* src = &Xb[(size_t)(kt + kr_[p]) * L_SEQ + n0 + cq_];
            unsigned dst = sBase + (unsigned)(((STAGES + s) * TS_ + kr_[p] * LDS_ + cq_) << 2);
            asm volatile("cp.async.cg.shared.global [%0], [%1], 16;\n" :: "r"(dst), "l"(src));
        }
    };

    #pragma unroll
    for (int t = 0; t < STAGES - 1; t++) {
        if (t < T) issue(t, t);
        asm volatile("cp.async.commit_group;\n");
    }

    int stage = 0;
    for (int t = 0; t < T; t++) {
        asm volatile("cp.async.wait_group %0;\n" :: "n"(STAGES - 2));
        __syncthreads();

        int pf = t + STAGES - 1;
        if (pf < T) {
            int ps = pf % STAGES;
            issue(pf, ps);
        }
        asm volatile("cp.async.commit_group;\n");

        const float* Ab = As + stage * TS_;
        const float* Bb = Bs + stage * TS_;
        stage = (stage + 1 == STAGES) ? 0 : stage + 1;

        #pragma unroll
        for (int kk = 0; kk < 32; kk += 8) {
            unsigned a[2][4];
            #pragma unroll
            for (int i = 0; i < 2; i++) {
                int mr = wm + i * 16;
                a[i][0] = __float_as_uint(Ab[(kk + tq)     * LDS_ + mr + g]);
                a[i][1] = __float_as_uint(Ab[(kk + tq)     * LDS_ + mr + g + 8]);
                a[i][2] = __float_as_uint(Ab[(kk + tq + 4) * LDS_ + mr + g]);
                a[i][3] = __float_as_uint(Ab[(kk + tq + 4) * LDS_ + mr + g + 8]);
            }
            unsigned bb[8][2];
            #pragma unroll
            for (int j = 0; j < 8; j++) {
                bb[j][0] = __float_as_uint(Bb[(kk + tq)     * LDS_ + wn + j * 8 + g]);
                bb[j][1] = __float_as_uint(Bb[(kk + tq + 4) * LDS_ + wn + j * 8 + g]);
            }
            #pragma unroll
            for (int i = 0; i < 2; i++)
                #pragma unroll
                for (int j = 0; j < 8; j++) {
                    asm("mma.sync.aligned.m16n8k8.row.col.f32.tf32.tf32.f32 "
                        "{%0,%1,%2,%3}, {%4,%5,%6,%7}, {%8,%9}, {%0,%1,%2,%3};\n"
                        : "+f"(acc[i][j][0]), "+f"(acc[i][j][1]),
                          "+f"(acc[i][j][2]), "+f"(acc[i][j][3])
                        : "r"(a[i][0]), "r"(a[i][1]), "r"(a[i][2]), "r"(a[i][3]),
                          "r"(bb[j][0]), "r"(bb[j][1]));
                }
        }
    }

    #pragma unroll
    for (int i = 0; i < 2; i++) {
        int r0 = wm + i * 16 + g;
        float bv0 = bias[mloc + r0];
        float bv1 = bias[mloc + r0 + 8];
        #pragma unroll
        for (int j = 0; j < 8; j++) {
            int col = n0 + wn + j * 8 + tq * 2;
            float2 v01 = make_float2(acc[i][j][0] + bv0, acc[i][j][1] + bv0);
            float2 v23 = make_float2(acc[i][j][2] + bv1, acc[i][j][3] + bv1);
            if (roundOut) {
                v01.x = rnd_tf32(v01.x); v01.y = rnd_tf32(v01.y);
                v23.x = rnd_tf32(v23.x); v23.y = rnd_tf32(v23.y);
            }
            *reinterpret_cast<float2*>(&Ob[(size_t)(m0 + r0)     * L_SEQ + col]) = v01;
            *reinterpret_cast<float2*>(&Ob[(size_t)(m0 + r0 + 8) * L_SEQ + col]) = v23;
        }
    }
}

// ---------------------------------------------------------------------------
// Attention: per (b, h, 128 consecutive l). Writes tf32-rounded att2 in the
// scrambled layout att2[b, h*64 + (l>>5), (l&31)*64 + d].
// ---------------------------------------------------------------------------
__global__ void __launch_bounds__(128) attn_kernel(float* __restrict__ att2)
{
    __shared__ float att_s[4][2048];
    const int b = blockIdx.z, h = blockIdx.y;
    const int l0 = blockIdx.x * 128;
    const int t = threadIdx.x;
    const int l = l0 + t;
    const float* base = g_qkv + (size_t)b * 3 * DMODEL * L_SEQ;
    const float* Q = base;
    const float* K = base + (size_t)DMODEL * L_SEQ;
    const float* V = base + (size_t)2 * DMODEL * L_SEQ;
    const int c0 = h * 64;

    float lg0 = 0.f, lg1 = 0.f, lg2 = 0.f;
    #pragma unroll 8
    for (int d = 0; d < 64; d++) {
        int cp = c0 + d;
        float qv = Q[(size_t)cp * L_SEQ + l];
        int f = 3 * cp;
        #pragma unroll
        for (int w = 0; w < 3; w++) {
            int ff = f + w;
            int cc = ff & 1023;
            int ll = l + (ff >> 10) - 1;
            float kv = (ll >= 0 && ll < L_SEQ) ? K[(size_t)cc * L_SEQ + ll] : 0.f;
            if (w == 0) lg0 += qv * kv;
            else if (w == 1) lg1 += qv * kv;
            else lg2 += qv * kv;
        }
    }
    float m  = fmaxf(lg0, fmaxf(lg1, lg2));
    float e0 = expf((lg0 - m) * 0.125f);
    float e1 = expf((lg1 - m) * 0.125f);
    float e2 = expf((lg2 - m) * 0.125f);
    float inv = 1.f / (e0 + e1 + e2);
    float a0 = e0 * inv, a1 = e1 * inv, a2 = e2 * inv;

    const int r = t >> 5, ln = t & 31;
    #pragma unroll 8
    for (int d = 0; d < 64; d++) {
        int cp = c0 + d;
        int f = 3 * cp;
        float s = 0.f;
        #pragma unroll
        for (int w = 0; w < 3; w++) {
            int ff = f + w;
            int cc = ff & 1023;
            int ll = l + (ff >> 10) - 1;
            float vv = (ll >= 0 && ll < L_SEQ) ? V[(size_t)cc * L_SEQ + ll] : 0.f;
            s += (w == 0 ? a0 : (w == 1 ? a1 : a2)) * vv;
        }
        att_s[r][ln * 64 + (d ^ ln)] = rnd_tf32(s);   // tf32-rounded for GEMM2
    }
    __syncthreads();

    float* out = att2 + (size_t)b * DMODEL * L_SEQ
                      + (size_t)(h * 64 + (l0 >> 5)) * L_SEQ;
    for (int j = t; j < 4 * 2048; j += 128) {
        int rr  = j >> 11;
        int col = j & 2047;
        int llx = col >> 6;
        int dd  = col & 63;
        out[(size_t)rr * L_SEQ + col] = att_s[rr][(llx << 6) + (dd ^ llx)];
    }
}

// ---------------------------------------------------------------------------
extern "C" void kernel_launch(void* const* d_in, const int* in_sizes, int n_in,
                              void* d_out, int out_size)
{
    const float* x  = (const float*)d_in[0];
    const float* wq = (const float*)d_in[1];
    const float* bq = (const float*)d_in[2];
    const float* wk = (const float*)d_in[3];
    const float* bk = (const float*)d_in[4];
    const float* wv = (const float*)d_in[5];
    const float* bv = (const float*)d_in[6];
    const float* wo = (const float*)d_in[7];
    const float* bo = (const float*)d_in[8];
    float* out = (float*)d_out;

    float* qkv;  cudaGetSymbolAddress((void**)&qkv,  g_qkv);
    float* att2; cudaGetSymbolAddress((void**)&att2, g_att2);
    float* xr;   cudaGetSymbolAddress((void**)&xr,   g_xr);
    float* wr;   cudaGetSymbolAddress((void**)&wr,   g_wr);

    // Pre-convert inputs/weights to tf32-rounded fp32.
    cvt_x_kernel<<<1024, 256>>>(x, xr, (int)((size_t)BATCH * NHID_C * L_SEQ / 4));
    cvt_w_kernel<<<512, 256>>>(wq, wk, wv, wo, wr);

    const float* wqr = wr;
    const float* wkr = wr + 524288;
    const float* wvr = wr + 2 * 524288;
    const float* wor = wr + 3 * 524288;

    const int smemBytes = STAGES * 2 * TS_ * (int)sizeof(float);  // 104448
    cudaFuncSetAttribute(gemm_tf32_kernel,
                         cudaFuncAttributeMaxDynamicSharedMemorySize, smemBytes);

    // GEMM1: QKV projections. M = 3072 (q|k|v), K = 512, N = 2048, per batch.
    gemm_tf32_kernel<<<dim3(16, 24, BATCH), 256, smemBytes>>>(
        xr, (size_t)NHID_C * L_SEQ,
        wqr, wkr, wvr, bq, bk, bv,
        qkv, (size_t)3 * DMODEL * L_SEQ,
        NHID_C, DMODEL, 1);

    // Attention: 16 l-tiles x 16 heads x 8 batches.
    attn_kernel<<<dim3(16, 16, BATCH), 128>>>(att2);

    // GEMM3: output projection. M = 512, K = 1024, N = 2048, per batch.
    gemm_tf32_kernel<<<dim3(16, 4, BATCH), 256, smemBytes>>>(
        att2, (size_t)DMODEL * L_SEQ,
        wor, wor, wor, bo, bo, bo,
        out, (size_t)NHID_C * L_SEQ,
        DMODEL, NHID_C, 0);
}

// round 10
// speedup vs baseline: 1.6502x; 1.0299x over previous
#include <cuda_runtime.h>
#include <cstdint>
#include <cstddef>

#define L_SEQ  2048
#define NHID_C 512
#define DMODEL 1024
#define BATCH  8

// Scratch (allocation-free)
__device__ float g_qkv [(size_t)BATCH * 3 * DMODEL * L_SEQ];   // tf32-rounded
__device__ float g_att2[(size_t)BATCH * DMODEL * L_SEQ];       // tf32-rounded
__device__ float g_xr  [(size_t)BATCH * NHID_C * L_SEQ];       // tf32-rounded x
__device__ float g_wr  [4 * 512 * 1024];                       // wq|wk|wv|wo tf32

__device__ __forceinline__ unsigned f2tf32(float x) {
    unsigned r;
    asm("cvt.rna.tf32.f32 %0, %1;" : "=r"(r) : "f"(x));
    return r;
}
__device__ __forceinline__ float rnd_tf32(float x) {
    return __uint_as_float(f2tf32(x));
}

// ---------------------------------------------------------------------------
// Pre-convert kernels: fp32 -> tf32-rounded fp32 (vectorized).
// ---------------------------------------------------------------------------
__global__ void cvt_x_kernel(const float* __restrict__ src, float* __restrict__ dst, int n4)
{
    int i = blockIdx.x * blockDim.x + threadIdx.x;
    int stride = gridDim.x * blockDim.x;
    for (; i < n4; i += stride) {
        float4 v = reinterpret_cast<const float4*>(src)[i];
        v.x = rnd_tf32(v.x); v.y = rnd_tf32(v.y);
        v.z = rnd_tf32(v.z); v.w = rnd_tf32(v.w);
        reinterpret_cast<float4*>(dst)[i] = v;
    }
}

__global__ void cvt_w_kernel(const float* __restrict__ w0, const float* __restrict__ w1,
                             const float* __restrict__ w2, const float* __restrict__ w3,
                             float* __restrict__ dst)
{
    int i = blockIdx.x * blockDim.x + threadIdx.x;
    int stride = gridDim.x * blockDim.x;
    for (; i < 4 * 131072; i += stride) {
        int seg = i >> 17;
        int loc = i & 131071;
        const float* s = (seg == 0) ? w0 : (seg == 1) ? w1 : (seg == 2) ? w2 : w3;
        float4 v = reinterpret_cast<const float4*>(s)[loc];
        v.x = rnd_tf32(v.x); v.y = rnd_tf32(v.y);
        v.z = rnd_tf32(v.z); v.w = rnd_tf32(v.w);
        reinterpret_cast<float4*>(dst)[i] = v;
    }
}

// ---------------------------------------------------------------------------
// Batched GEMM:  O[b, m, n] = sum_k W[k, m] * X[b, k, n] + bias[m]
// Operands pre-rounded to tf32. CTA tile 128x128x32, 4 warps (2x2),
// warp tile 64x64, mma m16n8k8 tf32. 3-stage cp.async pipeline, 2 CTAs/SM.
// ---------------------------------------------------------------------------
#define LDS_   136
#define TS_    (32 * LDS_)
#define STAGES 3

__global__ void __launch_bounds__(128, 2) gemm_tf32_kernel(
    const float* __restrict__ X, size_t xStrideB,
    const float* __restrict__ W0, const float* __restrict__ W1, const float* __restrict__ W2,
    const float* __restrict__ bias0, const float* __restrict__ bias1, const float* __restrict__ bias2,
    float* __restrict__ O, size_t oStrideB,
    int Kdim, int Mper, int roundOut)
{
    extern __shared__ float smem[];
    float* As = smem;
    float* Bs = smem + STAGES * TS_;

    const int b  = blockIdx.z;
    const int m0 = blockIdx.y * 128;
    const int n0 = blockIdx.x * 128;
    const int widx = m0 / Mper;
    const float* W    = (widx == 0) ? W0 : ((widx == 1) ? W1 : W2);
    const float* bias = (widx == 0) ? bias0 : ((widx == 1) ? bias1 : bias2);
    const int mloc = m0 - widx * Mper;
    const float* Xb = X + (size_t)b * xStrideB;
    float*       Ob = O + (size_t)b * oStrideB;

    const int tid  = threadIdx.x;
    const int warp = tid >> 5, lane = tid & 31;
    const int wm = (warp >> 1) * 64;     // 2 warps along M
    const int wn = (warp & 1) * 64;      // 2 warps along N
    const int g  = lane >> 2;
    const int tq = lane & 3;

    const unsigned sBase = (unsigned)__cvta_generic_to_shared(smem);

    float acc[4][8][4];
    #pragma unroll
    for (int i = 0; i < 4; i++)
        #pragma unroll
        for (int j = 0; j < 8; j++)
            #pragma unroll
            for (int r = 0; r < 4; r++) acc[i][j][r] = 0.f;

    const int T = Kdim >> 5;

    // copy: 1024 float4 per side, 128 threads -> 8 chunks each
    auto issue = [&](int t, int s) {
        const int kt = t << 5;
        #pragma unroll
        for (int p = 0; p < 8; p++) {
            int e  = p * 128 + tid;
            int kr = e >> 5;
            int cq = (e & 31) << 2;
            const float* srcA = &W[(size_t)(kt + kr) * Mper + mloc + cq];
            unsigned dstA = sBase + (unsigned)((s * TS_ + kr * LDS_ + cq) << 2);
            asm volatile("cp.async.ca.shared.global [%0], [%1], 16;\n" :: "r"(dstA), "l"(srcA));
            const float* srcB = &Xb[(size_t)(kt + kr) * L_SEQ + n0 + cq];
            unsigned dstB = sBase + (unsigned)(((STAGES + s) * TS_ + kr * LDS_ + cq) << 2);
            asm volatile("cp.async.cg.shared.global [%0], [%1], 16;\n" :: "r"(dstB), "l"(srcB));
        }
    };

    #pragma unroll
    for (int t = 0; t < STAGES - 1; t++) {
        if (t < T) issue(t, t);
        asm volatile("cp.async.commit_group;\n");
    }

    int stage = 0;
    for (int t = 0; t < T; t++) {
        asm volatile("cp.async.wait_group %0;\n" :: "n"(STAGES - 2));
        __syncthreads();

        int pf = t + STAGES - 1;
        if (pf < T) issue(pf, pf % STAGES);
        asm volatile("cp.async.commit_group;\n");

        const float* Ab = As + stage * TS_;
        const float* Bb = Bs + stage * TS_;
        stage = (stage + 1 == STAGES) ? 0 : stage + 1;

        #pragma unroll
        for (int kk = 0; kk < 32; kk += 8) {
            unsigned a[4][4];
            #pragma unroll
            for (int i = 0; i < 4; i++) {
                int mr = wm + i * 16;
                a[i][0] = __float_as_uint(Ab[(kk + tq)     * LDS_ + mr + g]);
                a[i][1] = __float_as_uint(Ab[(kk + tq)     * LDS_ + mr + g + 8]);
                a[i][2] = __float_as_uint(Ab[(kk + tq + 4) * LDS_ + mr + g]);
                a[i][3] = __float_as_uint(Ab[(kk + tq + 4) * LDS_ + mr + g + 8]);
            }
            unsigned bb[8][2];
            #pragma unroll
            for (int j = 0; j < 8; j++) {
                bb[j][0] = __float_as_uint(Bb[(kk + tq)     * LDS_ + wn + j * 8 + g]);
                bb[j][1] = __float_as_uint(Bb[(kk + tq + 4) * LDS_ + wn + j * 8 + g]);
            }
            #pragma unroll
            for (int i = 0; i < 4; i++)
                #pragma unroll
                for (int j = 0; j < 8; j++) {
                    asm("mma.sync.aligned.m16n8k8.row.col.f32.tf32.tf32.f32 "
                        "{%0,%1,%2,%3}, {%4,%5,%6,%7}, {%8,%9}, {%0,%1,%2,%3};\n"
                        : "+f"(acc[i][j][0]), "+f"(acc[i][j][1]),
                          "+f"(acc[i][j][2]), "+f"(acc[i][j][3])
                        : "r"(a[i][0]), "r"(a[i][1]), "r"(a[i][2]), "r"(a[i][3]),
                          "r"(bb[j][0]), "r"(bb[j][1]));
                }
        }
    }

    #pragma unroll
    for (int i = 0; i < 4; i++) {
        int r0 = wm + i * 16 + g;
        float bv0 = bias[mloc + r0];
        float bv1 = bias[mloc + r0 + 8];
        #pragma unroll
        for (int j = 0; j < 8; j++) {
            int col = n0 + wn + j * 8 + tq * 2;
            float2 v01 = make_float2(acc[i][j][0] + bv0, acc[i][j][1] + bv0);
            float2 v23 = make_float2(acc[i][j][2] + bv1, acc[i][j][3] + bv1);
            if (roundOut) {
                v01.x = rnd_tf32(v01.x); v01.y = rnd_tf32(v01.y);
                v23.x = rnd_tf32(v23.x); v23.y = rnd_tf32(v23.y);
            }
            *reinterpret_cast<float2*>(&Ob[(size_t)(m0 + r0)     * L_SEQ + col]) = v01;
            *reinterpret_cast<float2*>(&Ob[(size_t)(m0 + r0 + 8) * L_SEQ + col]) = v23;
        }
    }
}

// ---------------------------------------------------------------------------
// Attention: per (b, h, 128 consecutive l). Writes tf32-rounded att2 in the
// scrambled layout att2[b, h*64 + (l>>5), (l&31)*64 + d].
// ---------------------------------------------------------------------------
__global__ void __launch_bounds__(128) attn_kernel(float* __restrict__ att2)
{
    __shared__ float att_s[4][2048];
    const int b = blockIdx.z, h = blockIdx.y;
    const int l0 = blockIdx.x * 128;
    const int t = threadIdx.x;
    const int l = l0 + t;
    const float* base = g_qkv + (size_t)b * 3 * DMODEL * L_SEQ;
    const float* Q = base;
    const float* K = base + (size_t)DMODEL * L_SEQ;
    const float* V = base + (size_t)2 * DMODEL * L_SEQ;
    const int c0 = h * 64;

    float lg0 = 0.f, lg1 = 0.f, lg2 = 0.f;
    #pragma unroll 8
    for (int d = 0; d < 64; d++) {
        int cp = c0 + d;
        float qv = Q[(size_t)cp * L_SEQ + l];
        int f = 3 * cp;
        #pragma unroll
        for (int w = 0; w < 3; w++) {
            int ff = f + w;
            int cc = ff & 1023;
            int ll = l + (ff >> 10) - 1;
            float kv = (ll >= 0 && ll < L_SEQ) ? K[(size_t)cc * L_SEQ + ll] : 0.f;
            if (w == 0) lg0 += qv * kv;
            else if (w == 1) lg1 += qv * kv;
            else lg2 += qv * kv;
        }
    }
    float m  = fmaxf(lg0, fmaxf(lg1, lg2));
    float e0 = expf((lg0 - m) * 0.125f);
    float e1 = expf((lg1 - m) * 0.125f);
    float e2 = expf((lg2 - m) * 0.125f);
    float inv = 1.f / (e0 + e1 + e2);
    float a0 = e0 * inv, a1 = e1 * inv, a2 = e2 * inv;

    const int r = t >> 5, ln = t & 31;
    #pragma unroll 8
    for (int d = 0; d < 64; d++) {
        int cp = c0 + d;
        int f = 3 * cp;
        float s = 0.f;
        #pragma unroll
        for (int w = 0; w < 3; w++) {
            int ff = f + w;
            int cc = ff & 1023;
            int ll = l + (ff >> 10) - 1;
            float vv = (ll >= 0 && ll < L_SEQ) ? V[(size_t)cc * L_SEQ + ll] : 0.f;
            s += (w == 0 ? a0 : (w == 1 ? a1 : a2)) * vv;
        }
        att_s[r][ln * 64 + (d ^ ln)] = rnd_tf32(s);   // tf32-rounded for GEMM2
    }
    __syncthreads();

    float* out = att2 + (size_t)b * DMODEL * L_SEQ
                      + (size_t)(h * 64 + (l0 >> 5)) * L_SEQ;
    for (int j = t; j < 4 * 2048; j += 128) {
        int rr  = j >> 11;
        int col = j & 2047;
        int llx = col >> 6;
        int dd  = col & 63;
        out[(size_t)rr * L_SEQ + col] = att_s[rr][(llx << 6) + (dd ^ llx)];
    }
}

// ---------------------------------------------------------------------------
extern "C" void kernel_launch(void* const* d_in, const int* in_sizes, int n_in,
                              void* d_out, int out_size)
{
    const float* x  = (const float*)d_in[0];
    const float* wq = (const float*)d_in[1];
    const float* bq = (const float*)d_in[2];
    const float* wk = (const float*)d_in[3];
    const float* bk = (const float*)d_in[4];
    const float* wv = (const float*)d_in[5];
    const float* bv = (const float*)d_in[6];
    const float* wo = (const float*)d_in[7];
    const float* bo = (const float*)d_in[8];
    float* out = (float*)d_out;

    float* qkv;  cudaGetSymbolAddress((void**)&qkv,  g_qkv);
    float* att2; cudaGetSymbolAddress((void**)&att2, g_att2);
    float* xr;   cudaGetSymbolAddress((void**)&xr,   g_xr);
    float* wr;   cudaGetSymbolAddress((void**)&wr,   g_wr);

    // Pre-convert inputs/weights to tf32-rounded fp32.
    cvt_x_kernel<<<1024, 256>>>(x, xr, (int)((size_t)BATCH * NHID_C * L_SEQ / 4));
    cvt_w_kernel<<<512, 256>>>(wq, wk, wv, wo, wr);

    const float* wqr = wr;
    const float* wkr = wr + 524288;
    const float* wvr = wr + 2 * 524288;
    const float* wor = wr + 3 * 524288;

    const int smemBytes = STAGES * 2 * TS_ * (int)sizeof(float);  // 104448
    cudaFuncSetAttribute(gemm_tf32_kernel,
                         cudaFuncAttributeMaxDynamicSharedMemorySize, smemBytes);

    // GEMM1: QKV projections. M = 3072 (q|k|v), K = 512, N = 2048, per batch.
    gemm_tf32_kernel<<<dim3(16, 24, BATCH), 128, smemBytes>>>(
        xr, (size_t)NHID_C * L_SEQ,
        wqr, wkr, wvr, bq, bk, bv,
        qkv, (size_t)3 * DMODEL * L_SEQ,
        NHID_C, DMODEL, 1);

    // Attention: 16 l-tiles x 16 heads x 8 batches.
    attn_kernel<<<dim3(16, 16, BATCH), 128>>>(att2);

    // GEMM3: output projection. M = 512, K = 1024, N = 2048, per batch.
    gemm_tf32_kernel<<<dim3(16, 4, BATCH), 128, smemBytes>>>(
        att2, (size_t)DMODEL * L_SEQ,
        wor, wor, wor, bo, bo, bo,
        out, (size_t)NHID_C * L_SEQ,
        DMODEL, NHID_C, 0);
}